// round 8
// baseline (speedup 1.0000x reference)
#include <cuda_runtime.h>
#include <cuda_bf16.h>
#include <math.h>
#include <stdint.h>

#define NN 50000
#define EE 800000
#define GG 128
#define HH 128
#define CC 10
#define BCAP 64   // per-node neighbor bucket capacity (max degree ~35)

// ---------------- scratch (__device__ globals; no allocs allowed) ------------
__device__ float g_agg[2][NN * HH];
__device__ float g_hA[2][NN * HH];
__device__ float g_hB[2][NN * HH];
__device__ float g_pool[2][GG * HH];
__device__ float g_cnt[2][GG];
__device__ int g_bcnt[2][NN];
__device__ int g_bsrc[2][NN * BCAP];
// pre-split weights: [matrix][hi/lo][128n * 68u32]
// slots: 0,1 = c1W1 ens0/1 ; 2,3 = c1W2 ens0/1 ; 4..6 = csW1 l ; 7..9 = csW2 l
__device__ uint32_t g_wsplit[10][2][8704];

// ---------------- small helpers ----------------
__device__ __forceinline__ uint32_t pack2(__nv_bfloat16 a, __nv_bfloat16 b) {
    return (uint32_t)__bfloat16_as_ushort(a) |
           ((uint32_t)__bfloat16_as_ushort(b) << 16);
}
__device__ __forceinline__ void bsplit(float v, __nv_bfloat16& h, __nv_bfloat16& l) {
    h = __float2bfloat16_rn(v);
    l = __float2bfloat16_rn(v - __bfloat162float(h));
}

#define MMA16816(c, a0, a1, a2, a3, b0, b1)                                  \
    asm volatile(                                                            \
        "mma.sync.aligned.m16n8k16.row.col.f32.bf16.bf16.f32 "               \
        "{%0,%1,%2,%3}, {%4,%5,%6,%7}, {%8,%9}, {%0,%1,%2,%3};"              \
        : "+f"(c[0]), "+f"(c[1]), "+f"(c[2]), "+f"(c[3])                     \
        : "r"(a0), "r"(a1), "r"(a2), "r"(a3), "r"(b0), "r"(b1))

// ------- merged init: blocks 0..9 pre-split weights; rest zero counters -----
__global__ void init_prep_kernel(const float* __restrict__ c1W1,
                                 const float* __restrict__ c1W2,
                                 const float* __restrict__ csW1,
                                 const float* __restrict__ csW2) {
    if (blockIdx.x < 10) {
        int b = blockIdx.x;
        const float* W;
        if (b < 2)       W = c1W1 + (size_t)b * 16384;
        else if (b < 4)  W = c1W2 + (size_t)(b - 2) * 16384;
        else if (b < 7)  W = csW1 + (size_t)(b - 4) * 16384;
        else             W = csW2 + (size_t)(b - 7) * 16384;
        __nv_bfloat16* whb = (__nv_bfloat16*)g_wsplit[b][0];
        __nv_bfloat16* wlb = (__nv_bfloat16*)g_wsplit[b][1];
        const float4* Wv = (const float4*)W;
        for (int idx = threadIdx.x; idx < 4096; idx += 256) {
            int k = idx >> 5, nq = idx & 31;
            float4 v = Wv[k * 32 + nq];
            float vv[4] = {v.x, v.y, v.z, v.w};
#pragma unroll
            for (int i = 0; i < 4; i++) {
                int n = 4 * nq + i;
                __nv_bfloat16 h, l;
                bsplit(vv[i], h, l);
                whb[n * 136 + k] = h;   // W^T: [n][k], stride 136 bf16
                wlb[n * 136 + k] = l;
            }
        }
    } else {
        int i = (blockIdx.x - 10) * 256 + threadIdx.x;
        if (i < 2 * NN) g_bcnt[0][i] = 0;          // contiguous [2][NN]
        if (i < 2 * GG * HH) g_pool[0][i] = 0.f;
        if (i < 2 * GG) g_cnt[0][i] = 0.f;
    }
}

// ---------------- bucket fill ----------------
__global__ void fill_kernel(const int* __restrict__ ei) {
    int idx = blockIdx.x * 256 + threadIdx.x;
    if (idx < 2 * EE) {
        int ens = idx >= EE;
        int e = idx - ens * EE;
        const int* base = ei + (size_t)ens * 2 * EE;
        int d = base[EE + e];
        int slot = atomicAdd(&g_bcnt[ens][d], 1);
        g_bsrc[ens][(size_t)d * BCAP + slot] = base[e];
    }
}

// warp per node: agg[n] = (1+eps)*x[n] + sum_{j in N(n)} x[j]
// 8-wide independent load chains to hide L2 latency (MLP=8)
__global__ void agg_kernel(const float* __restrict__ xbase,
                           float* __restrict__ aggbase,
                           const float* __restrict__ eps_p, int eps_stride) {
    unsigned idx = blockIdx.x * 256u + threadIdx.x;
    unsigned wn = idx >> 5;
    unsigned c = idx & 31u;
    if (wn >= 2 * NN) return;
    int ens = wn >= NN;
    unsigned n = wn - (unsigned)ens * NN;
    float e1 = 1.0f + eps_p[ens * eps_stride];
    const float4* xv = (const float4*)(xbase + (size_t)ens * NN * HH);
    const int* __restrict__ bucket = &g_bsrc[ens][(size_t)n * BCAP];
    int deg = g_bcnt[ens][n];
    float4 s = xv[(size_t)n * 32 + c];
    s.x *= e1; s.y *= e1; s.z *= e1; s.w *= e1;
    int e = 0;
    for (; e + 7 < deg; e += 8) {
        int i0 = __ldg(&bucket[e]);
        int i1 = __ldg(&bucket[e + 1]);
        int i2 = __ldg(&bucket[e + 2]);
        int i3 = __ldg(&bucket[e + 3]);
        int i4 = __ldg(&bucket[e + 4]);
        int i5 = __ldg(&bucket[e + 5]);
        int i6 = __ldg(&bucket[e + 6]);
        int i7 = __ldg(&bucket[e + 7]);
        float4 v0 = xv[(size_t)(unsigned)i0 * 32 + c];
        float4 v1 = xv[(size_t)(unsigned)i1 * 32 + c];
        float4 v2 = xv[(size_t)(unsigned)i2 * 32 + c];
        float4 v3 = xv[(size_t)(unsigned)i3 * 32 + c];
        float4 v4 = xv[(size_t)(unsigned)i4 * 32 + c];
        float4 v5 = xv[(size_t)(unsigned)i5 * 32 + c];
        float4 v6 = xv[(size_t)(unsigned)i6 * 32 + c];
        float4 v7 = xv[(size_t)(unsigned)i7 * 32 + c];
        s.x += ((v0.x + v1.x) + (v2.x + v3.x)) + ((v4.x + v5.x) + (v6.x + v7.x));
        s.y += ((v0.y + v1.y) + (v2.y + v3.y)) + ((v4.y + v5.y) + (v6.y + v7.y));
        s.z += ((v0.z + v1.z) + (v2.z + v3.z)) + ((v4.z + v5.z) + (v6.z + v7.z));
        s.w += ((v0.w + v1.w) + (v2.w + v3.w)) + ((v4.w + v5.w) + (v6.w + v7.w));
    }
    for (; e + 3 < deg; e += 4) {
        int i0 = __ldg(&bucket[e]);
        int i1 = __ldg(&bucket[e + 1]);
        int i2 = __ldg(&bucket[e + 2]);
        int i3 = __ldg(&bucket[e + 3]);
        float4 v0 = xv[(size_t)(unsigned)i0 * 32 + c];
        float4 v1 = xv[(size_t)(unsigned)i1 * 32 + c];
        float4 v2 = xv[(size_t)(unsigned)i2 * 32 + c];
        float4 v3 = xv[(size_t)(unsigned)i3 * 32 + c];
        s.x += (v0.x + v1.x) + (v2.x + v3.x);
        s.y += (v0.y + v1.y) + (v2.y + v3.y);
        s.z += (v0.z + v1.z) + (v2.z + v3.z);
        s.w += (v0.w + v1.w) + (v2.w + v3.w);
    }
    for (; e < deg; e++) {
        int sn = __ldg(&bucket[e]);
        float4 v = xv[(size_t)(unsigned)sn * 32 + c];
        s.x += v.x; s.y += v.y; s.z += v.z; s.w += v.w;
    }
    ((float4*)(aggbase + (size_t)ens * NN * HH))[(size_t)n * 32 + c] = s;
}

// ---------------- MLP: split-bf16 mma.sync, 128-row tiles, 32x64 warp tiles -
// smem u32: AH[8704] AL[8704] WH[8704] WL[8704] prm[512] = 35328 u32 (141.3KB)
#define MLP_SMEM_U32 35328

__device__ __forceinline__ void copy_w(const uint32_t* __restrict__ gh,
                                       const uint32_t* __restrict__ gl,
                                       uint32_t* wh, uint32_t* wl, int tid) {
    const uint4* gh4 = (const uint4*)gh;
    const uint4* gl4 = (const uint4*)gl;
    uint4* wh4 = (uint4*)wh;
    uint4* wl4 = (uint4*)wl;
    for (int i = tid; i < 2176; i += 256) {
        wh4[i] = gh4[i];
        wl4[i] = gl4[i];
    }
}

// 32x64 warp tile: rows r0+16*rs (+8), cols nbase + 8j + ...
__device__ __forceinline__ void do_gemm(const uint32_t* __restrict__ AH,
                                        const uint32_t* __restrict__ AL,
                                        const uint32_t* __restrict__ WH,
                                        const uint32_t* __restrict__ WL,
                                        int r0, int nbase, int tg, int tp,
                                        float acc[2][8][4]) {
#pragma unroll
    for (int c = 0; c < 8; c++) {
        int ko = tp + 8 * c;
        uint32_t ah[2][4], al[2][4];
#pragma unroll
        for (int rs = 0; rs < 2; rs++) {
            int ar = (r0 + 16 * rs) * 68;
            int ar8 = ar + 8 * 68;
            ah[rs][0] = AH[ar + ko];      ah[rs][1] = AH[ar8 + ko];
            ah[rs][2] = AH[ar + ko + 4];  ah[rs][3] = AH[ar8 + ko + 4];
            al[rs][0] = AL[ar + ko];      al[rs][1] = AL[ar8 + ko];
            al[rs][2] = AL[ar + ko + 4];  al[rs][3] = AL[ar8 + ko + 4];
        }
#pragma unroll
        for (int j = 0; j < 8; j++) {
            int nb = (nbase + 8 * j + tg) * 68 + ko;
            uint32_t bh0 = WH[nb], bh1 = WH[nb + 4];
            uint32_t bl0 = WL[nb], bl1 = WL[nb + 4];
#pragma unroll
            for (int rs = 0; rs < 2; rs++) {
                MMA16816(acc[rs][j], ah[rs][0], ah[rs][1], ah[rs][2], ah[rs][3], bh0, bh1);
                MMA16816(acc[rs][j], ah[rs][0], ah[rs][1], ah[rs][2], ah[rs][3], bl0, bl1);
                MMA16816(acc[rs][j], al[rs][0], al[rs][1], al[rs][2], al[rs][3], bh0, bh1);
            }
        }
    }
}

__global__ __launch_bounds__(256) void mlp_kernel(
    const float* __restrict__ Abase, float* __restrict__ outbase,
    int w1slot, int w1stride, int w2slot, int w2stride,
    const float* __restrict__ b1, const float* __restrict__ b2,
    const float* __restrict__ gamma, const float* __restrict__ beta,
    const float* __restrict__ mean, const float* __restrict__ var, int vs) {
    extern __shared__ uint32_t sm32[];
    uint32_t* AH = sm32;
    uint32_t* AL = sm32 + 8704;
    uint32_t* WH = sm32 + 17408;
    uint32_t* WL = sm32 + 26112;
    float* b1s = (float*)(sm32 + 34816);
    float* b2s = b1s + 128;
    float* scs = b2s + 128;
    float* shs = scs + 128;

    int ens = blockIdx.y;
    const float* A = Abase + (size_t)ens * NN * HH;
    b1 += ens * vs;  b2 += ens * vs;
    gamma += ens * vs;  beta += ens * vs;  mean += ens * vs;  var += ens * vs;
    int s1 = w1slot + ens * w1stride;
    int s2 = w2slot + ens * w2stride;

    int tid = threadIdx.x;
    int wid = tid >> 5, t = tid & 31, tg = t >> 2, tp = t & 3;
    int wm = wid & 3, wcol = wid >> 2;
    int rb = blockIdx.x * 128;

    if (tid < 128) {
        b1s[tid] = b1[tid];
        b2s[tid] = b2[tid];
        float sc = gamma[tid] * rsqrtf(var[tid] + 1e-5f);
        scs[tid] = sc;
        shs[tid] = beta[tid] - mean[tid] * sc;
    }

    // stage A tile (128 rows) split hi/lo
    {
        const float4* Av = (const float4*)A;
        uint2* ahv = (uint2*)AH;
        uint2* alv = (uint2*)AL;
        for (int idx = tid; idx < 4096; idx += 256) {
            int r = idx >> 5, q = idx & 31;
            int gr = rb + r;
            float4 v = (gr < NN) ? Av[(size_t)gr * 32 + q]
                                 : make_float4(0.f, 0.f, 0.f, 0.f);
            __nv_bfloat16 hx, lx, hy, ly, hz, lz, hw, lw;
            bsplit(v.x, hx, lx); bsplit(v.y, hy, ly);
            bsplit(v.z, hz, lz); bsplit(v.w, hw, lw);
            ahv[r * 34 + q] = make_uint2(pack2(hx, hy), pack2(hz, hw));
            alv[r * 34 + q] = make_uint2(pack2(lx, ly), pack2(lz, lw));
        }
    }
    copy_w(g_wsplit[s1][0], g_wsplit[s1][1], WH, WL, tid);
    __syncthreads();

    float acc[2][8][4];
#pragma unroll
    for (int rs = 0; rs < 2; rs++)
#pragma unroll
        for (int j = 0; j < 8; j++)
#pragma unroll
            for (int q = 0; q < 4; q++) acc[rs][j][q] = 0.f;

    int r0 = wm * 32 + tg;
    int nbase = wcol * 64;

    do_gemm(AH, AL, WH, WL, r0, nbase, tg, tp, acc);
    __syncthreads();

    // epilogue 1: h1 = relu(acc + b1) -> back into AH/AL (own rows/cols)
#pragma unroll
    for (int rs = 0; rs < 2; rs++) {
        int arow = (r0 + 16 * rs) * 68;
        int arow8 = arow + 8 * 68;
#pragma unroll
        for (int j = 0; j < 8; j++) {
            int col0 = nbase + 8 * j + 2 * tp;
            int cu = col0 >> 1;
            float bb0 = b1s[col0], bb1 = b1s[col0 + 1];
            float v0 = fmaxf(acc[rs][j][0] + bb0, 0.f);
            float v1 = fmaxf(acc[rs][j][1] + bb1, 0.f);
            float v2 = fmaxf(acc[rs][j][2] + bb0, 0.f);
            float v3 = fmaxf(acc[rs][j][3] + bb1, 0.f);
            __nv_bfloat16 h0, l0, h1b, l1b, h2, l2, h3, l3;
            bsplit(v0, h0, l0); bsplit(v1, h1b, l1b);
            bsplit(v2, h2, l2); bsplit(v3, h3, l3);
            AH[arow + cu] = pack2(h0, h1b);
            AL[arow + cu] = pack2(l0, l1b);
            AH[arow8 + cu] = pack2(h2, h3);
            AL[arow8 + cu] = pack2(l2, l3);
            acc[rs][j][0] = acc[rs][j][1] = acc[rs][j][2] = acc[rs][j][3] = 0.f;
        }
    }
    copy_w(g_wsplit[s2][0], g_wsplit[s2][1], WH, WL, tid);
    __syncthreads();

    do_gemm(AH, AL, WH, WL, r0, nbase, tg, tp, acc);

    // final epilogue: relu -> BN -> relu -> global
    float* out = outbase + (size_t)ens * NN * HH;
#pragma unroll
    for (int rs = 0; rs < 2; rs++) {
        int gr0 = rb + r0 + 16 * rs;
        int gr8 = gr0 + 8;
#pragma unroll
        for (int j = 0; j < 8; j++) {
            int col0 = nbase + 8 * j + 2 * tp;
            float bb0 = b2s[col0], bb1 = b2s[col0 + 1];
            float s0 = scs[col0], s1f = scs[col0 + 1];
            float t0 = shs[col0], t1 = shs[col0 + 1];
            float v0 = fmaxf(acc[rs][j][0] + bb0, 0.f);
            float v1 = fmaxf(acc[rs][j][1] + bb1, 0.f);
            float v2 = fmaxf(acc[rs][j][2] + bb0, 0.f);
            float v3 = fmaxf(acc[rs][j][3] + bb1, 0.f);
            float o0 = fmaxf(v0 * s0 + t0, 0.f);
            float o1 = fmaxf(v1 * s1f + t1, 0.f);
            float o2 = fmaxf(v2 * s0 + t0, 0.f);
            float o3 = fmaxf(v3 * s1f + t1, 0.f);
            if (gr0 < NN)
                *(float2*)(out + (size_t)gr0 * HH + col0) = make_float2(o0, o1);
            if (gr8 < NN)
                *(float2*)(out + (size_t)gr8 * HH + col0) = make_float2(o2, o3);
        }
    }
}

// ---------------- pool + head ----------------
__global__ void pool_kernel(const float* __restrict__ hbase,
                            const int* __restrict__ batch) {
    unsigned idx = blockIdx.x * 256u + threadIdx.x;
    unsigned wn = idx >> 5;
    unsigned c = (idx & 31u) << 2;
    if (wn >= 2 * NN) return;
    int ens = wn >= NN;
    unsigned n = wn - (unsigned)ens * NN;
    int g = batch[(size_t)ens * NN + n];
    const float* h = hbase + (size_t)ens * NN * HH;
    float4 v = *(const float4*)(h + (size_t)n * HH + c);
    atomicAdd((float4*)(&g_pool[ens][g * HH + c]), v);
    if (c == 0) atomicAdd(&g_cnt[ens][g], 1.0f);
}

__global__ void head_kernel(const float* __restrict__ W1all,
                            const float* __restrict__ b1all,
                            const float* __restrict__ W2all,
                            const float* __restrict__ b2all,
                            float* __restrict__ out) {
    int g = blockIdx.x;
    int ens = blockIdx.y;
    int c = threadIdx.x;  // 128 threads
    const float* W1 = W1all + (size_t)ens * 16384;
    const float* b1 = b1all + ens * 128;
    const float* W2 = W2all + (size_t)ens * 1280;
    const float* b2 = b2all + ens * 10;
    __shared__ float p[128];
    __shared__ float z[128];
    float cn = fmaxf(g_cnt[ens][g], 1.0f);
    p[c] = g_pool[ens][g * HH + c] / cn;
    __syncthreads();
    float acc = b1[c];
#pragma unroll 4
    for (int k = 0; k < 128; k++) acc += p[k] * W1[k * 128 + c];
    z[c] = fmaxf(acc, 0.f);
    __syncthreads();
    if (c < CC) {
        float y = b2[c];
#pragma unroll 4
        for (int k = 0; k < 128; k++) y += z[k] * W2[k * CC + c];
        out[((size_t)ens * GG + g) * CC + c] = y;
    }
}

// ---------------- driver ----------------
extern "C" void kernel_launch(void* const* d_in, const int* in_sizes, int n_in,
                              void* d_out, int out_size) {
    const float* x     = (const float*)d_in[0];
    const int*   ei    = (const int*)d_in[1];
    const int*   batch = (const int*)d_in[2];
    const float* c1W1  = (const float*)d_in[3];
    const float* c1b1  = (const float*)d_in[4];
    const float* c1W2  = (const float*)d_in[5];
    const float* c1b2  = (const float*)d_in[6];
    const float* c1g   = (const float*)d_in[7];
    const float* c1be  = (const float*)d_in[8];
    const float* c1m   = (const float*)d_in[9];
    const float* c1v   = (const float*)d_in[10];
    const float* c1e   = (const float*)d_in[11];
    const float* csW1  = (const float*)d_in[12];
    const float* csb1  = (const float*)d_in[13];
    const float* csW2  = (const float*)d_in[14];
    const float* csb2  = (const float*)d_in[15];
    const float* csg   = (const float*)d_in[16];
    const float* csbe  = (const float*)d_in[17];
    const float* csm   = (const float*)d_in[18];
    const float* csv   = (const float*)d_in[19];
    const float* cse   = (const float*)d_in[20];
    const float* l1W   = (const float*)d_in[21];
    const float* l1b   = (const float*)d_in[22];
    const float* l2W   = (const float*)d_in[23];
    const float* l2b   = (const float*)d_in[24];
    float* out = (float*)d_out;

    float *agg, *hA, *hB;
    cudaGetSymbolAddress((void**)&agg, g_agg);
    cudaGetSymbolAddress((void**)&hA, g_hA);
    cudaGetSymbolAddress((void**)&hB, g_hB);

    const int SMEM_BYTES = MLP_SMEM_U32 * 4;  // 141,312 B
    cudaFuncSetAttribute(mlp_kernel, cudaFuncAttributeMaxDynamicSharedMemorySize,
                         SMEM_BYTES);

    const int IP_GRID   = 10 + (2 * NN + 255) / 256;  // prep blocks + zero blocks
    const int E_GRID    = (2 * EE + 255) / 256;
    const int AGG_GRID  = (2 * NN * 32 + 255) / 256;
    const dim3 MLP_GRID((NN + 127) / 128, 2);
    const int POOL_GRID = (2 * NN * 32 + 255) / 256;

    // 1: init+prep, 2: fill, 3: agg, 4: mlp (profiled slot)
    init_prep_kernel<<<IP_GRID, 256>>>(c1W1, c1W2, csW1, csW2);
    fill_kernel<<<E_GRID, 256>>>(ei);

    // layer 0 (conv1, per-ensemble weights: slots 0+ens / 2+ens)
    agg_kernel<<<AGG_GRID, 256>>>(x, agg, c1e, 1);
    mlp_kernel<<<MLP_GRID, 256, SMEM_BYTES>>>(
        agg, hA, 0, 1, 2, 1, c1b1, c1b2, c1g, c1be, c1m, c1v, 128);

    // layers 1..3 (shared weights: slots 4+l / 7+l)
    const float* cur = hA;
    float* nxt = hB;
    for (int l = 0; l < 3; l++) {
        agg_kernel<<<AGG_GRID, 256>>>(cur, agg, cse + l, 0);
        mlp_kernel<<<MLP_GRID, 256, SMEM_BYTES>>>(
            agg, nxt, 4 + l, 0, 7 + l, 0,
            csb1 + l * 128, csb2 + l * 128,
            csg + l * 128, csbe + l * 128, csm + l * 128, csv + l * 128, 0);
        const float* tswap = cur;
        cur = nxt;
        nxt = (float*)tswap;
    }

    pool_kernel<<<POOL_GRID, 256>>>(cur, batch);
    head_kernel<<<dim3(GG, 2), 128>>>(l1W, l1b, l2W, l2b, out);
}

// round 9
// speedup vs baseline: 1.1454x; 1.1454x over previous
#include <cuda_runtime.h>
#include <cuda_bf16.h>
#include <cuda_fp16.h>
#include <math.h>
#include <stdint.h>

#define NN 50000
#define EE 800000
#define GG 128
#define HH 128
#define CC 10
#define BCAP 64   // per-node neighbor bucket capacity (max degree ~35)

// ---------------- scratch (__device__ globals; no allocs allowed) ------------
__device__ float g_agg[2][NN * HH];          // fp32 MLP input
__device__ float g_hF[2][NN * HH];           // fp32 final-layer output (pool)
__device__ __half g_x16[2][NN * HH];         // fp16 copy of x for gather
__device__ __half g_h16A[2][NN * HH];        // fp16 inter-layer activations
__device__ __half g_h16B[2][NN * HH];
__device__ float g_pool[2][GG * HH];
__device__ float g_cnt[2][GG];
__device__ int g_bcnt[2][NN];
__device__ int g_bsrc[2][NN * BCAP];
// pre-split weights: [matrix][hi/lo][128n * 68u32]
// slots: 0,1 = c1W1 ens0/1 ; 2,3 = c1W2 ens0/1 ; 4..6 = csW1 l ; 7..9 = csW2 l
__device__ uint32_t g_wsplit[10][2][8704];

// ---------------- small helpers ----------------
__device__ __forceinline__ uint32_t pack2(__nv_bfloat16 a, __nv_bfloat16 b) {
    return (uint32_t)__bfloat16_as_ushort(a) |
           ((uint32_t)__bfloat16_as_ushort(b) << 16);
}
__device__ __forceinline__ void bsplit(float v, __nv_bfloat16& h, __nv_bfloat16& l) {
    h = __float2bfloat16_rn(v);
    l = __float2bfloat16_rn(v - __bfloat162float(h));
}

#define MMA16816(c, a0, a1, a2, a3, b0, b1)                                  \
    asm volatile(                                                            \
        "mma.sync.aligned.m16n8k16.row.col.f32.bf16.bf16.f32 "               \
        "{%0,%1,%2,%3}, {%4,%5,%6,%7}, {%8,%9}, {%0,%1,%2,%3};"              \
        : "+f"(c[0]), "+f"(c[1]), "+f"(c[2]), "+f"(c[3])                     \
        : "r"(a0), "r"(a1), "r"(a2), "r"(a3), "r"(b0), "r"(b1))

// ------- merged init: blocks 0..9 pre-split weights; rest zero counters -----
__global__ void init_prep_kernel(const float* __restrict__ c1W1,
                                 const float* __restrict__ c1W2,
                                 const float* __restrict__ csW1,
                                 const float* __restrict__ csW2) {
    if (blockIdx.x < 10) {
        int b = blockIdx.x;
        const float* W;
        if (b < 2)       W = c1W1 + (size_t)b * 16384;
        else if (b < 4)  W = c1W2 + (size_t)(b - 2) * 16384;
        else if (b < 7)  W = csW1 + (size_t)(b - 4) * 16384;
        else             W = csW2 + (size_t)(b - 7) * 16384;
        __nv_bfloat16* whb = (__nv_bfloat16*)g_wsplit[b][0];
        __nv_bfloat16* wlb = (__nv_bfloat16*)g_wsplit[b][1];
        const float4* Wv = (const float4*)W;
        for (int idx = threadIdx.x; idx < 4096; idx += 256) {
            int k = idx >> 5, nq = idx & 31;
            float4 v = Wv[k * 32 + nq];
            float vv[4] = {v.x, v.y, v.z, v.w};
#pragma unroll
            for (int i = 0; i < 4; i++) {
                int n = 4 * nq + i;
                __nv_bfloat16 h, l;
                bsplit(vv[i], h, l);
                whb[n * 136 + k] = h;   // W^T: [n][k], stride 136 bf16
                wlb[n * 136 + k] = l;
            }
        }
    } else {
        int i = (blockIdx.x - 10) * 256 + threadIdx.x;
        if (i < 2 * NN) g_bcnt[0][i] = 0;          // contiguous [2][NN]
        if (i < 2 * GG * HH) g_pool[0][i] = 0.f;
        if (i < 2 * GG) g_cnt[0][i] = 0.f;
    }
}

// ---------------- x -> fp16 conversion (8 elems/thread) ----------------
__global__ void x16_kernel(const float* __restrict__ x) {
    size_t i = ((size_t)blockIdx.x * 256 + threadIdx.x) * 8;  // < 12.8M exact
    float4 a = *(const float4*)(x + i);
    float4 b = *(const float4*)(x + i + 4);
    __half2 h0 = __floats2half2_rn(a.x, a.y);
    __half2 h1 = __floats2half2_rn(a.z, a.w);
    __half2 h2 = __floats2half2_rn(b.x, b.y);
    __half2 h3 = __floats2half2_rn(b.z, b.w);
    uint4 o;
    o.x = *(uint32_t*)&h0; o.y = *(uint32_t*)&h1;
    o.z = *(uint32_t*)&h2; o.w = *(uint32_t*)&h3;
    *(uint4*)((__half*)g_x16 + i) = o;
}

// ---------------- bucket fill ----------------
__global__ void fill_kernel(const int* __restrict__ ei) {
    int idx = blockIdx.x * 256 + threadIdx.x;
    if (idx < 2 * EE) {
        int ens = idx >= EE;
        int e = idx - ens * EE;
        const int* base = ei + (size_t)ens * 2 * EE;
        int d = base[EE + e];
        int slot = atomicAdd(&g_bcnt[ens][d], 1);
        g_bsrc[ens][(size_t)d * BCAP + slot] = base[e];
    }
}

// warp per node: agg[n] = (1+eps)*x[n] + sum_{j in N(n)} x[j]
// fp16 gather (256B/edge, halved L2 traffic), fp32 accumulate + fp32 agg out
__device__ __forceinline__ void h4acc(uint2 p, float& s0, float& s1,
                                      float& s2, float& s3) {
    __half2 a = *(__half2*)&p.x;
    __half2 b = *(__half2*)&p.y;
    float2 fa = __half22float2(a);
    float2 fb = __half22float2(b);
    s0 += fa.x; s1 += fa.y; s2 += fb.x; s3 += fb.y;
}

__global__ void agg_kernel(const __half* __restrict__ xbase,
                           float* __restrict__ aggbase,
                           const float* __restrict__ eps_p, int eps_stride) {
    unsigned idx = blockIdx.x * 256u + threadIdx.x;
    unsigned wn = idx >> 5;
    unsigned c = idx & 31u;
    if (wn >= 2 * NN) return;
    int ens = wn >= NN;
    unsigned n = wn - (unsigned)ens * NN;
    float e1 = 1.0f + eps_p[ens * eps_stride];
    const uint2* xv = (const uint2*)(xbase + (size_t)ens * NN * HH);  // 32/row
    const int* __restrict__ bucket = &g_bsrc[ens][(size_t)n * BCAP];
    int deg = g_bcnt[ens][n];
    float s0 = 0.f, s1 = 0.f, s2 = 0.f, s3 = 0.f;
    {   // self term
        uint2 p = __ldg(&xv[(size_t)n * 32 + c]);
        h4acc(p, s0, s1, s2, s3);
        s0 *= e1; s1 *= e1; s2 *= e1; s3 *= e1;
    }
    int e = 0;
    for (; e + 3 < deg; e += 4) {
        int i0 = __ldg(&bucket[e]);
        int i1 = __ldg(&bucket[e + 1]);
        int i2 = __ldg(&bucket[e + 2]);
        int i3 = __ldg(&bucket[e + 3]);
        uint2 p0 = __ldg(&xv[(size_t)(unsigned)i0 * 32 + c]);
        uint2 p1 = __ldg(&xv[(size_t)(unsigned)i1 * 32 + c]);
        uint2 p2 = __ldg(&xv[(size_t)(unsigned)i2 * 32 + c]);
        uint2 p3 = __ldg(&xv[(size_t)(unsigned)i3 * 32 + c]);
        h4acc(p0, s0, s1, s2, s3);
        h4acc(p1, s0, s1, s2, s3);
        h4acc(p2, s0, s1, s2, s3);
        h4acc(p3, s0, s1, s2, s3);
    }
    for (; e < deg; e++) {
        int sn = __ldg(&bucket[e]);
        uint2 p = __ldg(&xv[(size_t)(unsigned)sn * 32 + c]);
        h4acc(p, s0, s1, s2, s3);
    }
    ((float4*)(aggbase + (size_t)ens * NN * HH))[(size_t)n * 32 + c] =
        make_float4(s0, s1, s2, s3);
}

// ---------------- MLP: split-bf16 mma.sync, 128-row tiles, 32x64 warp tiles -
// smem u32: AH[8704] AL[8704] WH[8704] WL[8704] prm[512] = 35328 u32 (141.3KB)
#define MLP_SMEM_U32 35328

__device__ __forceinline__ void copy_w(const uint32_t* __restrict__ gh,
                                       const uint32_t* __restrict__ gl,
                                       uint32_t* wh, uint32_t* wl, int tid) {
    const uint4* gh4 = (const uint4*)gh;
    const uint4* gl4 = (const uint4*)gl;
    uint4* wh4 = (uint4*)wh;
    uint4* wl4 = (uint4*)wl;
    for (int i = tid; i < 2176; i += 256) {
        wh4[i] = gh4[i];
        wl4[i] = gl4[i];
    }
}

// 32x64 warp tile: rows r0+16*rs (+8), cols nbase + 8j + ...
__device__ __forceinline__ void do_gemm(const uint32_t* __restrict__ AH,
                                        const uint32_t* __restrict__ AL,
                                        const uint32_t* __restrict__ WH,
                                        const uint32_t* __restrict__ WL,
                                        int r0, int nbase, int tg, int tp,
                                        float acc[2][8][4]) {
#pragma unroll
    for (int c = 0; c < 8; c++) {
        int ko = tp + 8 * c;
        uint32_t ah[2][4], al[2][4];
#pragma unroll
        for (int rs = 0; rs < 2; rs++) {
            int ar = (r0 + 16 * rs) * 68;
            int ar8 = ar + 8 * 68;
            ah[rs][0] = AH[ar + ko];      ah[rs][1] = AH[ar8 + ko];
            ah[rs][2] = AH[ar + ko + 4];  ah[rs][3] = AH[ar8 + ko + 4];
            al[rs][0] = AL[ar + ko];      al[rs][1] = AL[ar8 + ko];
            al[rs][2] = AL[ar + ko + 4];  al[rs][3] = AL[ar8 + ko + 4];
        }
#pragma unroll
        for (int j = 0; j < 8; j++) {
            int nb = (nbase + 8 * j + tg) * 68 + ko;
            uint32_t bh0 = WH[nb], bh1 = WH[nb + 4];
            uint32_t bl0 = WL[nb], bl1 = WL[nb + 4];
#pragma unroll
            for (int rs = 0; rs < 2; rs++) {
                MMA16816(acc[rs][j], ah[rs][0], ah[rs][1], ah[rs][2], ah[rs][3], bh0, bh1);
                MMA16816(acc[rs][j], ah[rs][0], ah[rs][1], ah[rs][2], ah[rs][3], bl0, bl1);
                MMA16816(acc[rs][j], al[rs][0], al[rs][1], al[rs][2], al[rs][3], bh0, bh1);
            }
        }
    }
}

__global__ __launch_bounds__(256) void mlp_kernel(
    const float* __restrict__ Abase, float* __restrict__ outbase,
    __half* __restrict__ out16base,
    int w1slot, int w1stride, int w2slot, int w2stride,
    const float* __restrict__ b1, const float* __restrict__ b2,
    const float* __restrict__ gamma, const float* __restrict__ beta,
    const float* __restrict__ mean, const float* __restrict__ var, int vs) {
    extern __shared__ uint32_t sm32[];
    uint32_t* AH = sm32;
    uint32_t* AL = sm32 + 8704;
    uint32_t* WH = sm32 + 17408;
    uint32_t* WL = sm32 + 26112;
    float* b1s = (float*)(sm32 + 34816);
    float* b2s = b1s + 128;
    float* scs = b2s + 128;
    float* shs = scs + 128;

    int ens = blockIdx.y;
    const float* A = Abase + (size_t)ens * NN * HH;
    b1 += ens * vs;  b2 += ens * vs;
    gamma += ens * vs;  beta += ens * vs;  mean += ens * vs;  var += ens * vs;
    int s1 = w1slot + ens * w1stride;
    int s2 = w2slot + ens * w2stride;

    int tid = threadIdx.x;
    int wid = tid >> 5, t = tid & 31, tg = t >> 2, tp = t & 3;
    int wm = wid & 3, wcol = wid >> 2;
    int rb = blockIdx.x * 128;

    if (tid < 128) {
        b1s[tid] = b1[tid];
        b2s[tid] = b2[tid];
        float sc = gamma[tid] * rsqrtf(var[tid] + 1e-5f);
        scs[tid] = sc;
        shs[tid] = beta[tid] - mean[tid] * sc;
    }

    // stage A tile (128 rows) split hi/lo
    {
        const float4* Av = (const float4*)A;
        uint2* ahv = (uint2*)AH;
        uint2* alv = (uint2*)AL;
        for (int idx = tid; idx < 4096; idx += 256) {
            int r = idx >> 5, q = idx & 31;
            int gr = rb + r;
            float4 v = (gr < NN) ? Av[(size_t)gr * 32 + q]
                                 : make_float4(0.f, 0.f, 0.f, 0.f);
            __nv_bfloat16 hx, lx, hy, ly, hz, lz, hw, lw;
            bsplit(v.x, hx, lx); bsplit(v.y, hy, ly);
            bsplit(v.z, hz, lz); bsplit(v.w, hw, lw);
            ahv[r * 34 + q] = make_uint2(pack2(hx, hy), pack2(hz, hw));
            alv[r * 34 + q] = make_uint2(pack2(lx, ly), pack2(lz, lw));
        }
    }
    copy_w(g_wsplit[s1][0], g_wsplit[s1][1], WH, WL, tid);
    __syncthreads();

    float acc[2][8][4];
#pragma unroll
    for (int rs = 0; rs < 2; rs++)
#pragma unroll
        for (int j = 0; j < 8; j++)
#pragma unroll
            for (int q = 0; q < 4; q++) acc[rs][j][q] = 0.f;

    int r0 = wm * 32 + tg;
    int nbase = wcol * 64;

    do_gemm(AH, AL, WH, WL, r0, nbase, tg, tp, acc);
    __syncthreads();

    // epilogue 1: h1 = relu(acc + b1) -> back into AH/AL (own rows/cols)
#pragma unroll
    for (int rs = 0; rs < 2; rs++) {
        int arow = (r0 + 16 * rs) * 68;
        int arow8 = arow + 8 * 68;
#pragma unroll
        for (int j = 0; j < 8; j++) {
            int col0 = nbase + 8 * j + 2 * tp;
            int cu = col0 >> 1;
            float bb0 = b1s[col0], bb1 = b1s[col0 + 1];
            float v0 = fmaxf(acc[rs][j][0] + bb0, 0.f);
            float v1 = fmaxf(acc[rs][j][1] + bb1, 0.f);
            float v2 = fmaxf(acc[rs][j][2] + bb0, 0.f);
            float v3 = fmaxf(acc[rs][j][3] + bb1, 0.f);
            __nv_bfloat16 h0, l0, h1b, l1b, h2, l2, h3, l3;
            bsplit(v0, h0, l0); bsplit(v1, h1b, l1b);
            bsplit(v2, h2, l2); bsplit(v3, h3, l3);
            AH[arow + cu] = pack2(h0, h1b);
            AL[arow + cu] = pack2(l0, l1b);
            AH[arow8 + cu] = pack2(h2, h3);
            AL[arow8 + cu] = pack2(l2, l3);
            acc[rs][j][0] = acc[rs][j][1] = acc[rs][j][2] = acc[rs][j][3] = 0.f;
        }
    }
    copy_w(g_wsplit[s2][0], g_wsplit[s2][1], WH, WL, tid);
    __syncthreads();

    do_gemm(AH, AL, WH, WL, r0, nbase, tg, tp, acc);

    // final epilogue: relu -> BN -> relu -> global (fp16 or fp32)
#pragma unroll
    for (int rs = 0; rs < 2; rs++) {
        int gr0 = rb + r0 + 16 * rs;
        int gr8 = gr0 + 8;
#pragma unroll
        for (int j = 0; j < 8; j++) {
            int col0 = nbase + 8 * j + 2 * tp;
            float bb0 = b2s[col0], bb1 = b2s[col0 + 1];
            float s0 = scs[col0], s1f = scs[col0 + 1];
            float t0 = shs[col0], t1 = shs[col0 + 1];
            float v0 = fmaxf(acc[rs][j][0] + bb0, 0.f);
            float v1 = fmaxf(acc[rs][j][1] + bb1, 0.f);
            float v2 = fmaxf(acc[rs][j][2] + bb0, 0.f);
            float v3 = fmaxf(acc[rs][j][3] + bb1, 0.f);
            float o0 = fmaxf(v0 * s0 + t0, 0.f);
            float o1 = fmaxf(v1 * s1f + t1, 0.f);
            float o2 = fmaxf(v2 * s0 + t0, 0.f);
            float o3 = fmaxf(v3 * s1f + t1, 0.f);
            if (out16base) {
                __half* o16 = out16base + (size_t)ens * NN * HH;
                if (gr0 < NN)
                    *(__half2*)(o16 + (size_t)gr0 * HH + col0) = __floats2half2_rn(o0, o1);
                if (gr8 < NN)
                    *(__half2*)(o16 + (size_t)gr8 * HH + col0) = __floats2half2_rn(o2, o3);
            } else {
                float* out = outbase + (size_t)ens * NN * HH;
                if (gr0 < NN)
                    *(float2*)(out + (size_t)gr0 * HH + col0) = make_float2(o0, o1);
                if (gr8 < NN)
                    *(float2*)(out + (size_t)gr8 * HH + col0) = make_float2(o2, o3);
            }
        }
    }
}

// ---------------- pool + head ----------------
__global__ void pool_kernel(const float* __restrict__ hbase,
                            const int* __restrict__ batch) {
    unsigned idx = blockIdx.x * 256u + threadIdx.x;
    unsigned wn = idx >> 5;
    unsigned c = (idx & 31u) << 2;
    if (wn >= 2 * NN) return;
    int ens = wn >= NN;
    unsigned n = wn - (unsigned)ens * NN;
    int g = batch[(size_t)ens * NN + n];
    const float* h = hbase + (size_t)ens * NN * HH;
    float4 v = *(const float4*)(h + (size_t)n * HH + c);
    atomicAdd((float4*)(&g_pool[ens][g * HH + c]), v);
    if (c == 0) atomicAdd(&g_cnt[ens][g], 1.0f);
}

__global__ void head_kernel(const float* __restrict__ W1all,
                            const float* __restrict__ b1all,
                            const float* __restrict__ W2all,
                            const float* __restrict__ b2all,
                            float* __restrict__ out) {
    int g = blockIdx.x;
    int ens = blockIdx.y;
    int c = threadIdx.x;  // 128 threads
    const float* W1 = W1all + (size_t)ens * 16384;
    const float* b1 = b1all + ens * 128;
    const float* W2 = W2all + (size_t)ens * 1280;
    const float* b2 = b2all + ens * 10;
    __shared__ float p[128];
    __shared__ float z[128];
    float cn = fmaxf(g_cnt[ens][g], 1.0f);
    p[c] = g_pool[ens][g * HH + c] / cn;
    __syncthreads();
    float acc = b1[c];
#pragma unroll 4
    for (int k = 0; k < 128; k++) acc += p[k] * W1[k * 128 + c];
    z[c] = fmaxf(acc, 0.f);
    __syncthreads();
    if (c < CC) {
        float y = b2[c];
#pragma unroll 4
        for (int k = 0; k < 128; k++) y += z[k] * W2[k * CC + c];
        out[((size_t)ens * GG + g) * CC + c] = y;
    }
}

// ---------------- driver ----------------
extern "C" void kernel_launch(void* const* d_in, const int* in_sizes, int n_in,
                              void* d_out, int out_size) {
    const float* x     = (const float*)d_in[0];
    const int*   ei    = (const int*)d_in[1];
    const int*   batch = (const int*)d_in[2];
    const float* c1W1  = (const float*)d_in[3];
    const float* c1b1  = (const float*)d_in[4];
    const float* c1W2  = (const float*)d_in[5];
    const float* c1b2  = (const float*)d_in[6];
    const float* c1g   = (const float*)d_in[7];
    const float* c1be  = (const float*)d_in[8];
    const float* c1m   = (const float*)d_in[9];
    const float* c1v   = (const float*)d_in[10];
    const float* c1e   = (const float*)d_in[11];
    const float* csW1  = (const float*)d_in[12];
    const float* csb1  = (const float*)d_in[13];
    const float* csW2  = (const float*)d_in[14];
    const float* csb2  = (const float*)d_in[15];
    const float* csg   = (const float*)d_in[16];
    const float* csbe  = (const float*)d_in[17];
    const float* csm   = (const float*)d_in[18];
    const float* csv   = (const float*)d_in[19];
    const float* cse   = (const float*)d_in[20];
    const float* l1W   = (const float*)d_in[21];
    const float* l1b   = (const float*)d_in[22];
    const float* l2W   = (const float*)d_in[23];
    const float* l2b   = (const float*)d_in[24];
    float* out = (float*)d_out;

    float *agg, *hF;
    __half *x16, *h16A, *h16B;
    cudaGetSymbolAddress((void**)&agg, g_agg);
    cudaGetSymbolAddress((void**)&hF, g_hF);
    cudaGetSymbolAddress((void**)&x16, g_x16);
    cudaGetSymbolAddress((void**)&h16A, g_h16A);
    cudaGetSymbolAddress((void**)&h16B, g_h16B);

    const int SMEM_BYTES = MLP_SMEM_U32 * 4;  // 141,312 B
    cudaFuncSetAttribute(mlp_kernel, cudaFuncAttributeMaxDynamicSharedMemorySize,
                         SMEM_BYTES);

    const int IP_GRID   = 10 + (2 * NN + 255) / 256;
    const int X16_GRID  = (2 * NN * HH) / (8 * 256);  // 12.8M exact
    const int E_GRID    = (2 * EE + 255) / 256;
    const int AGG_GRID  = (2 * NN * 32 + 255) / 256;
    const dim3 MLP_GRID((NN + 127) / 128, 2);
    const int POOL_GRID = (2 * NN * 32 + 255) / 256;

    init_prep_kernel<<<IP_GRID, 256>>>(c1W1, c1W2, csW1, csW2);
    x16_kernel<<<X16_GRID, 256>>>(x);
    fill_kernel<<<E_GRID, 256>>>(ei);

    // layer 0 (conv1, per-ensemble weights: slots 0+ens / 2+ens) -> fp16 out
    agg_kernel<<<AGG_GRID, 256>>>(x16, agg, c1e, 1);
    mlp_kernel<<<MLP_GRID, 256, SMEM_BYTES>>>(
        agg, nullptr, h16A, 0, 1, 2, 1, c1b1, c1b2, c1g, c1be, c1m, c1v, 128);

    // layers 1..2 (shared weights: slots 4+l / 7+l) -> fp16 out
    const __half* cur = h16A;
    __half* nxt = h16B;
    for (int l = 0; l < 2; l++) {
        agg_kernel<<<AGG_GRID, 256>>>(cur, agg, cse + l, 0);
        mlp_kernel<<<MLP_GRID, 256, SMEM_BYTES>>>(
            agg, nullptr, nxt, 4 + l, 0, 7 + l, 0,
            csb1 + l * 128, csb2 + l * 128,
            csg + l * 128, csbe + l * 128, csm + l * 128, csv + l * 128, 0);
        const __half* tswap = cur;
        cur = nxt;
        nxt = (__half*)tswap;
    }

    // layer 3: fp32 out for pool
    agg_kernel<<<AGG_GRID, 256>>>(cur, agg, cse + 2, 0);
    mlp_kernel<<<MLP_GRID, 256, SMEM_BYTES>>>(
        agg, hF, nullptr, 6, 0, 9, 0,
        csb1 + 2 * 128, csb2 + 2 * 128,
        csg + 2 * 128, csbe + 2 * 128, csm + 2 * 128, csv + 2 * 128, 0);

    pool_kernel<<<POOL_GRID, 256>>>(hF, batch);
    head_kernel<<<dim3(GG, 2), 128>>>(l1W, l1b, l2W, l2b, out);
}

// round 10
// speedup vs baseline: 1.4407x; 1.2578x over previous
#include <cuda_runtime.h>
#include <cuda_bf16.h>
#include <cuda_fp16.h>
#include <math.h>
#include <stdint.h>

#define NN 50000
#define EE 800000
#define GG 128
#define HH 128
#define CC 10
#define BCAP 64   // per-node neighbor bucket capacity (max degree ~35)

// ---------------- scratch (__device__ globals; no allocs allowed) ------------
__device__ __half g_agg16[2][NN * HH];       // fp16 MLP input (agg output)
__device__ float g_hF[2][NN * HH];           // fp32 final-layer output (pool)
__device__ __half g_x16[2][NN * HH];         // fp16 copy of x for gather
__device__ __half g_h16A[2][NN * HH];        // fp16 inter-layer activations
__device__ __half g_h16B[2][NN * HH];
__device__ float g_pool[2][GG * HH];
__device__ float g_cnt[2][GG];
__device__ int g_bcnt[2][NN];
__device__ int g_bsrc[2][NN * BCAP];
// pre-split fp16 weights: [matrix][hi/lo][128n * 68u32]
// slots: 0,1 = c1W1 ens0/1 ; 2,3 = c1W2 ens0/1 ; 4..6 = csW1 l ; 7..9 = csW2 l
__device__ uint32_t g_wsplit[10][2][8704];

// ---------------- small helpers ----------------
__device__ __forceinline__ void hsplit(float v, __half& h, __half& l) {
    h = __float2half_rn(v);
    l = __float2half_rn(v - __half2float(h));
}

// fp16 MMA, fp32 accumulate
#define MMAF16(c, a0, a1, a2, a3, b0, b1)                                    \
    asm volatile(                                                            \
        "mma.sync.aligned.m16n8k16.row.col.f32.f16.f16.f32 "                 \
        "{%0,%1,%2,%3}, {%4,%5,%6,%7}, {%8,%9}, {%0,%1,%2,%3};"              \
        : "+f"(c[0]), "+f"(c[1]), "+f"(c[2]), "+f"(c[3])                     \
        : "r"(a0), "r"(a1), "r"(a2), "r"(a3), "r"(b0), "r"(b1))

// ------- merged init: blocks 0..9 pre-split weights; rest zero counters -----
__global__ void init_prep_kernel(const float* __restrict__ c1W1,
                                 const float* __restrict__ c1W2,
                                 const float* __restrict__ csW1,
                                 const float* __restrict__ csW2) {
    if (blockIdx.x < 10) {
        int b = blockIdx.x;
        const float* W;
        if (b < 2)       W = c1W1 + (size_t)b * 16384;
        else if (b < 4)  W = c1W2 + (size_t)(b - 2) * 16384;
        else if (b < 7)  W = csW1 + (size_t)(b - 4) * 16384;
        else             W = csW2 + (size_t)(b - 7) * 16384;
        __half* whb = (__half*)g_wsplit[b][0];
        __half* wlb = (__half*)g_wsplit[b][1];
        const float4* Wv = (const float4*)W;
        for (int idx = threadIdx.x; idx < 4096; idx += 256) {
            int k = idx >> 5, nq = idx & 31;
            float4 v = Wv[k * 32 + nq];
            float vv[4] = {v.x, v.y, v.z, v.w};
#pragma unroll
            for (int i = 0; i < 4; i++) {
                int n = 4 * nq + i;
                __half h, l;
                hsplit(vv[i], h, l);
                whb[n * 136 + k] = h;   // W^T: [n][k], stride 136 half (68 u32)
                wlb[n * 136 + k] = l;
            }
        }
    } else {
        int i = (blockIdx.x - 10) * 256 + threadIdx.x;
        if (i < 2 * NN) g_bcnt[0][i] = 0;          // contiguous [2][NN]
        if (i < 2 * GG * HH) g_pool[0][i] = 0.f;
        if (i < 2 * GG) g_cnt[0][i] = 0.f;
    }
}

// ---------------- x -> fp16 conversion (8 elems/thread) ----------------
__global__ void x16_kernel(const float* __restrict__ x) {
    size_t i = ((size_t)blockIdx.x * 256 + threadIdx.x) * 8;  // < 12.8M exact
    float4 a = *(const float4*)(x + i);
    float4 b = *(const float4*)(x + i + 4);
    __half2 h0 = __floats2half2_rn(a.x, a.y);
    __half2 h1 = __floats2half2_rn(a.z, a.w);
    __half2 h2 = __floats2half2_rn(b.x, b.y);
    __half2 h3 = __floats2half2_rn(b.z, b.w);
    uint4 o;
    o.x = *(uint32_t*)&h0; o.y = *(uint32_t*)&h1;
    o.z = *(uint32_t*)&h2; o.w = *(uint32_t*)&h3;
    *(uint4*)((__half*)g_x16 + i) = o;
}

// ---------------- bucket fill ----------------
__global__ void fill_kernel(const int* __restrict__ ei) {
    int idx = blockIdx.x * 256 + threadIdx.x;
    if (idx < 2 * EE) {
        int ens = idx >= EE;
        int e = idx - ens * EE;
        const int* base = ei + (size_t)ens * 2 * EE;
        int d = base[EE + e];
        int slot = atomicAdd(&g_bcnt[ens][d], 1);
        g_bsrc[ens][(size_t)d * BCAP + slot] = base[e];
    }
}

// warp per node: agg[n] = (1+eps)*x[n] + sum_{j in N(n)} x[j]
// fp16 gather + HADD2 accumulation (4 chains), fp32 combine, fp16 out
__global__ void agg_kernel(const __half* __restrict__ xbase,
                           __half* __restrict__ aggbase,
                           const float* __restrict__ eps_p, int eps_stride) {
    unsigned idx = blockIdx.x * 256u + threadIdx.x;
    unsigned wn = idx >> 5;
    unsigned c = idx & 31u;
    if (wn >= 2 * NN) return;
    int ens = wn >= NN;
    unsigned n = wn - (unsigned)ens * NN;
    float e1 = 1.0f + eps_p[ens * eps_stride];
    const uint2* xv = (const uint2*)(xbase + (size_t)ens * NN * HH);  // 32/row
    const int* __restrict__ bucket = &g_bsrc[ens][(size_t)n * BCAP];
    int deg = g_bcnt[ens][n];

    __half2 za = __floats2half2_rn(0.f, 0.f);
    __half2 acc[4][2];
#pragma unroll
    for (int k = 0; k < 4; k++) { acc[k][0] = za; acc[k][1] = za; }

    uint2 self = __ldg(&xv[(size_t)n * 32 + c]);

    int e = 0;
    for (; e + 3 < deg; e += 4) {
        int i0 = __ldg(&bucket[e]);
        int i1 = __ldg(&bucket[e + 1]);
        int i2 = __ldg(&bucket[e + 2]);
        int i3 = __ldg(&bucket[e + 3]);
        uint2 p0 = __ldg(&xv[(size_t)(unsigned)i0 * 32 + c]);
        uint2 p1 = __ldg(&xv[(size_t)(unsigned)i1 * 32 + c]);
        uint2 p2 = __ldg(&xv[(size_t)(unsigned)i2 * 32 + c]);
        uint2 p3 = __ldg(&xv[(size_t)(unsigned)i3 * 32 + c]);
        acc[0][0] = __hadd2(acc[0][0], *(__half2*)&p0.x);
        acc[0][1] = __hadd2(acc[0][1], *(__half2*)&p0.y);
        acc[1][0] = __hadd2(acc[1][0], *(__half2*)&p1.x);
        acc[1][1] = __hadd2(acc[1][1], *(__half2*)&p1.y);
        acc[2][0] = __hadd2(acc[2][0], *(__half2*)&p2.x);
        acc[2][1] = __hadd2(acc[2][1], *(__half2*)&p2.y);
        acc[3][0] = __hadd2(acc[3][0], *(__half2*)&p3.x);
        acc[3][1] = __hadd2(acc[3][1], *(__half2*)&p3.y);
    }
    for (; e < deg; e++) {
        int sn = __ldg(&bucket[e]);
        uint2 p = __ldg(&xv[(size_t)(unsigned)sn * 32 + c]);
        acc[e & 3][0] = __hadd2(acc[e & 3][0], *(__half2*)&p.x);
        acc[e & 3][1] = __hadd2(acc[e & 3][1], *(__half2*)&p.y);
    }

    // combine 4 chains + (1+eps)*self in fp32
    float2 lo = make_float2(0.f, 0.f), hi = make_float2(0.f, 0.f);
#pragma unroll
    for (int k = 0; k < 4; k++) {
        float2 a = __half22float2(acc[k][0]);
        float2 b = __half22float2(acc[k][1]);
        lo.x += a.x; lo.y += a.y; hi.x += b.x; hi.y += b.y;
    }
    float2 sl = __half22float2(*(__half2*)&self.x);
    float2 sh = __half22float2(*(__half2*)&self.y);
    lo.x = fmaf(e1, sl.x, lo.x); lo.y = fmaf(e1, sl.y, lo.y);
    hi.x = fmaf(e1, sh.x, hi.x); hi.y = fmaf(e1, sh.y, hi.y);

    __half2 o0 = __floats2half2_rn(lo.x, lo.y);
    __half2 o1 = __floats2half2_rn(hi.x, hi.y);
    uint2 o;
    o.x = *(uint32_t*)&o0; o.y = *(uint32_t*)&o1;
    ((uint2*)(aggbase + (size_t)ens * NN * HH))[(size_t)n * 32 + c] = o;
}

// ---------------- MLP: fp16 A + fp16-split W, mma.sync, occ 2 ---------------
// smem u32: As[8704] WH[8704] WL[8704] prm[512] = 26624 u32 (106.5KB)
#define MLP_SMEM_U32 26624

__device__ __forceinline__ void copy_w(const uint32_t* __restrict__ gh,
                                       const uint32_t* __restrict__ gl,
                                       uint32_t* wh, uint32_t* wl, int tid) {
    const uint4* gh4 = (const uint4*)gh;
    const uint4* gl4 = (const uint4*)gl;
    uint4* wh4 = (uint4*)wh;
    uint4* wl4 = (uint4*)wl;
    for (int i = tid; i < 2176; i += 256) {
        wh4[i] = gh4[i];
        wl4[i] = gl4[i];
    }
}

// 32x64 warp tile: rows r0+16*rs (+8), cols nbase + 8j + ...
__device__ __forceinline__ void do_gemm(const uint32_t* __restrict__ As,
                                        const uint32_t* __restrict__ WH,
                                        const uint32_t* __restrict__ WL,
                                        int r0, int nbase, int tg, int tp,
                                        float acc[2][8][4]) {
#pragma unroll
    for (int c = 0; c < 8; c++) {
        int ko = tp + 8 * c;
        uint32_t ah[2][4];
#pragma unroll
        for (int rs = 0; rs < 2; rs++) {
            int ar = (r0 + 16 * rs) * 68;
            int ar8 = ar + 8 * 68;
            ah[rs][0] = As[ar + ko];      ah[rs][1] = As[ar8 + ko];
            ah[rs][2] = As[ar + ko + 4];  ah[rs][3] = As[ar8 + ko + 4];
        }
#pragma unroll
        for (int j = 0; j < 8; j++) {
            int nb = (nbase + 8 * j + tg) * 68 + ko;
            uint32_t bh0 = WH[nb], bh1 = WH[nb + 4];
            uint32_t bl0 = WL[nb], bl1 = WL[nb + 4];
#pragma unroll
            for (int rs = 0; rs < 2; rs++) {
                MMAF16(acc[rs][j], ah[rs][0], ah[rs][1], ah[rs][2], ah[rs][3], bh0, bh1);
                MMAF16(acc[rs][j], ah[rs][0], ah[rs][1], ah[rs][2], ah[rs][3], bl0, bl1);
            }
        }
    }
}

__global__ __launch_bounds__(256, 2) void mlp_kernel(
    const __half* __restrict__ Abase, float* __restrict__ outbase,
    __half* __restrict__ out16base,
    int w1slot, int w1stride, int w2slot, int w2stride,
    const float* __restrict__ b1, const float* __restrict__ b2,
    const float* __restrict__ gamma, const float* __restrict__ beta,
    const float* __restrict__ mean, const float* __restrict__ var, int vs) {
    extern __shared__ uint32_t sm32[];
    uint32_t* As = sm32;
    uint32_t* WH = sm32 + 8704;
    uint32_t* WL = sm32 + 17408;
    float* b1s = (float*)(sm32 + 26112);
    float* b2s = b1s + 128;
    float* scs = b2s + 128;
    float* shs = scs + 128;

    int ens = blockIdx.y;
    const __half* A = Abase + (size_t)ens * NN * HH;
    b1 += ens * vs;  b2 += ens * vs;
    gamma += ens * vs;  beta += ens * vs;  mean += ens * vs;  var += ens * vs;
    int s1 = w1slot + ens * w1stride;
    int s2 = w2slot + ens * w2stride;

    int tid = threadIdx.x;
    int wid = tid >> 5, t = tid & 31, tg = t >> 2, tp = t & 3;
    int wm = wid & 3, wcol = wid >> 2;
    int rb = blockIdx.x * 128;

    if (tid < 128) {
        b1s[tid] = b1[tid];
        b2s[tid] = b2[tid];
        float sc = gamma[tid] * rsqrtf(var[tid] + 1e-5f);
        scs[tid] = sc;
        shs[tid] = beta[tid] - mean[tid] * sc;
    }

    // stage A tile (128 rows x 128 halves), pure copy
    {
        const uint2* Av = (const uint2*)A;  // 32 uint2 per row
        uint2* As2 = (uint2*)As;            // stride 34 uint2
        for (int idx = tid; idx < 4096; idx += 256) {
            int r = idx >> 5, q = idx & 31;
            int gr = rb + r;
            uint2 v = (gr < NN) ? Av[(size_t)gr * 32 + q] : make_uint2(0u, 0u);
            As2[r * 34 + q] = v;
        }
    }
    copy_w(g_wsplit[s1][0], g_wsplit[s1][1], WH, WL, tid);
    __syncthreads();

    float acc[2][8][4];
#pragma unroll
    for (int rs = 0; rs < 2; rs++)
#pragma unroll
        for (int j = 0; j < 8; j++)
#pragma unroll
            for (int q = 0; q < 4; q++) acc[rs][j][q] = 0.f;

    int r0 = wm * 32 + tg;
    int nbase = wcol * 64;

    do_gemm(As, WH, WL, r0, nbase, tg, tp, acc);
    __syncthreads();

    // epilogue 1: h1 = relu(acc + b1) -> fp16 back into As (own rows/cols)
#pragma unroll
    for (int rs = 0; rs < 2; rs++) {
        int arow = (r0 + 16 * rs) * 68;
        int arow8 = arow + 8 * 68;
#pragma unroll
        for (int j = 0; j < 8; j++) {
            int col0 = nbase + 8 * j + 2 * tp;
            int cu = col0 >> 1;
            float bb0 = b1s[col0], bb1 = b1s[col0 + 1];
            float v0 = fmaxf(acc[rs][j][0] + bb0, 0.f);
            float v1 = fmaxf(acc[rs][j][1] + bb1, 0.f);
            float v2 = fmaxf(acc[rs][j][2] + bb0, 0.f);
            float v3 = fmaxf(acc[rs][j][3] + bb1, 0.f);
            __half2 p0 = __floats2half2_rn(v0, v1);
            __half2 p1 = __floats2half2_rn(v2, v3);
            As[arow + cu] = *(uint32_t*)&p0;
            As[arow8 + cu] = *(uint32_t*)&p1;
            acc[rs][j][0] = acc[rs][j][1] = acc[rs][j][2] = acc[rs][j][3] = 0.f;
        }
    }
    copy_w(g_wsplit[s2][0], g_wsplit[s2][1], WH, WL, tid);
    __syncthreads();

    do_gemm(As, WH, WL, r0, nbase, tg, tp, acc);

    // final epilogue: relu -> BN -> relu -> global (fp16 or fp32)
#pragma unroll
    for (int rs = 0; rs < 2; rs++) {
        int gr0 = rb + r0 + 16 * rs;
        int gr8 = gr0 + 8;
#pragma unroll
        for (int j = 0; j < 8; j++) {
            int col0 = nbase + 8 * j + 2 * tp;
            float bb0 = b2s[col0], bb1 = b2s[col0 + 1];
            float s0 = scs[col0], s1f = scs[col0 + 1];
            float t0 = shs[col0], t1 = shs[col0 + 1];
            float v0 = fmaxf(acc[rs][j][0] + bb0, 0.f);
            float v1 = fmaxf(acc[rs][j][1] + bb1, 0.f);
            float v2 = fmaxf(acc[rs][j][2] + bb0, 0.f);
            float v3 = fmaxf(acc[rs][j][3] + bb1, 0.f);
            float o0 = fmaxf(v0 * s0 + t0, 0.f);
            float o1 = fmaxf(v1 * s1f + t1, 0.f);
            float o2 = fmaxf(v2 * s0 + t0, 0.f);
            float o3 = fmaxf(v3 * s1f + t1, 0.f);
            if (out16base) {
                __half* o16 = out16base + (size_t)ens * NN * HH;
                if (gr0 < NN)
                    *(__half2*)(o16 + (size_t)gr0 * HH + col0) = __floats2half2_rn(o0, o1);
                if (gr8 < NN)
                    *(__half2*)(o16 + (size_t)gr8 * HH + col0) = __floats2half2_rn(o2, o3);
            } else {
                float* out = outbase + (size_t)ens * NN * HH;
                if (gr0 < NN)
                    *(float2*)(out + (size_t)gr0 * HH + col0) = make_float2(o0, o1);
                if (gr8 < NN)
                    *(float2*)(out + (size_t)gr8 * HH + col0) = make_float2(o2, o3);
            }
        }
    }
}

// ---------------- pool + head ----------------
__global__ void pool_kernel(const float* __restrict__ hbase,
                            const int* __restrict__ batch) {
    unsigned idx = blockIdx.x * 256u + threadIdx.x;
    unsigned wn = idx >> 5;
    unsigned c = (idx & 31u) << 2;
    if (wn >= 2 * NN) return;
    int ens = wn >= NN;
    unsigned n = wn - (unsigned)ens * NN;
    int g = batch[(size_t)ens * NN + n];
    const float* h = hbase + (size_t)ens * NN * HH;
    float4 v = *(const float4*)(h + (size_t)n * HH + c);
    atomicAdd((float4*)(&g_pool[ens][g * HH + c]), v);
    if (c == 0) atomicAdd(&g_cnt[ens][g], 1.0f);
}

__global__ void head_kernel(const float* __restrict__ W1all,
                            const float* __restrict__ b1all,
                            const float* __restrict__ W2all,
                            const float* __restrict__ b2all,
                            float* __restrict__ out) {
    int g = blockIdx.x;
    int ens = blockIdx.y;
    int c = threadIdx.x;  // 128 threads
    const float* W1 = W1all + (size_t)ens * 16384;
    const float* b1 = b1all + ens * 128;
    const float* W2 = W2all + (size_t)ens * 1280;
    const float* b2 = b2all + ens * 10;
    __shared__ float p[128];
    __shared__ float z[128];
    float cn = fmaxf(g_cnt[ens][g], 1.0f);
    p[c] = g_pool[ens][g * HH + c] / cn;
    __syncthreads();
    float acc = b1[c];
#pragma unroll 4
    for (int k = 0; k < 128; k++) acc += p[k] * W1[k * 128 + c];
    z[c] = fmaxf(acc, 0.f);
    __syncthreads();
    if (c < CC) {
        float y = b2[c];
#pragma unroll 4
        for (int k = 0; k < 128; k++) y += z[k] * W2[k * CC + c];
        out[((size_t)ens * GG + g) * CC + c] = y;
    }
}

// ---------------- driver ----------------
extern "C" void kernel_launch(void* const* d_in, const int* in_sizes, int n_in,
                              void* d_out, int out_size) {
    const float* x     = (const float*)d_in[0];
    const int*   ei    = (const int*)d_in[1];
    const int*   batch = (const int*)d_in[2];
    const float* c1W1  = (const float*)d_in[3];
    const float* c1b1  = (const float*)d_in[4];
    const float* c1W2  = (const float*)d_in[5];
    const float* c1b2  = (const float*)d_in[6];
    const float* c1g   = (const float*)d_in[7];
    const float* c1be  = (const float*)d_in[8];
    const float* c1m   = (const float*)d_in[9];
    const float* c1v   = (const float*)d_in[10];
    const float* c1e   = (const float*)d_in[11];
    const float* csW1  = (const float*)d_in[12];
    const float* csb1  = (const float*)d_in[13];
    const float* csW2  = (const float*)d_in[14];
    const float* csb2  = (const float*)d_in[15];
    const float* csg   = (const float*)d_in[16];
    const float* csbe  = (const float*)d_in[17];
    const float* csm   = (const float*)d_in[18];
    const float* csv   = (const float*)d_in[19];
    const float* cse   = (const float*)d_in[20];
    const float* l1W   = (const float*)d_in[21];
    const float* l1b   = (const float*)d_in[22];
    const float* l2W   = (const float*)d_in[23];
    const float* l2b   = (const float*)d_in[24];
    float* out = (float*)d_out;

    float* hF;
    __half *agg16, *x16, *h16A, *h16B;
    cudaGetSymbolAddress((void**)&agg16, g_agg16);
    cudaGetSymbolAddress((void**)&hF, g_hF);
    cudaGetSymbolAddress((void**)&x16, g_x16);
    cudaGetSymbolAddress((void**)&h16A, g_h16A);
    cudaGetSymbolAddress((void**)&h16B, g_h16B);

    const int SMEM_BYTES = MLP_SMEM_U32 * 4;  // 106,496 B (occ 2)
    cudaFuncSetAttribute(mlp_kernel, cudaFuncAttributeMaxDynamicSharedMemorySize,
                         SMEM_BYTES);

    const int IP_GRID   = 10 + (2 * NN + 255) / 256;
    const int X16_GRID  = (2 * NN * HH) / (8 * 256);  // 12.8M exact
    const int E_GRID    = (2 * EE + 255) / 256;
    const int AGG_GRID  = (2 * NN * 32 + 255) / 256;
    const dim3 MLP_GRID((NN + 127) / 128, 2);
    const int POOL_GRID = (2 * NN * 32 + 255) / 256;

    init_prep_kernel<<<IP_GRID, 256>>>(c1W1, c1W2, csW1, csW2);
    x16_kernel<<<X16_GRID, 256>>>(x);
    fill_kernel<<<E_GRID, 256>>>(ei);

    // layer 0 (conv1, per-ensemble weights: slots 0+ens / 2+ens) -> fp16 out
    agg_kernel<<<AGG_GRID, 256>>>(x16, agg16, c1e, 1);
    mlp_kernel<<<MLP_GRID, 256, SMEM_BYTES>>>(
        agg16, nullptr, h16A, 0, 1, 2, 1, c1b1, c1b2, c1g, c1be, c1m, c1v, 128);

    // layers 1..2 (shared weights: slots 4+l / 7+l) -> fp16 out
    const __half* cur = h16A;
    __half* nxt = h16B;
    for (int l = 0; l < 2; l++) {
        agg_kernel<<<AGG_GRID, 256>>>(cur, agg16, cse + l, 0);
        mlp_kernel<<<MLP_GRID, 256, SMEM_BYTES>>>(
            agg16, nullptr, nxt, 4 + l, 0, 7 + l, 0,
            csb1 + l * 128, csb2 + l * 128,
            csg + l * 128, csbe + l * 128, csm + l * 128, csv + l * 128, 0);
        const __half* tswap = cur;
        cur = nxt;
        nxt = (__half*)tswap;
    }

    // layer 3: fp32 out for pool
    agg_kernel<<<AGG_GRID, 256>>>(cur, agg16, cse + 2, 0);
    mlp_kernel<<<MLP_GRID, 256, SMEM_BYTES>>>(
        agg16, hF, nullptr, 6, 0, 9, 0,
        csb1 + 2 * 128, csb2 + 2 * 128,
        csg + 2 * 128, csbe + 2 * 128, csm + 2 * 128, csv + 2 * 128, 0);

    pool_kernel<<<POOL_GRID, 256>>>(hF, batch);
    head_kernel<<<dim3(GG, 2), 128>>>(l1W, l1b, l2W, l2b, out);
}